// round 15
// baseline (speedup 1.0000x reference)
#include <cuda_runtime.h>

#define B 4
#define N 8192
#define C 128
#define S 2048
#define K 32
#define D 256      // 2C
#define CP 132     // C+3 padded
#define R2 0.01f
#define CAP 256
#define NFPS 4
#define NWORK 144
#define NCTA 148
#define NCELL 512  // 8x8x8 grid
#define TPB 1024

// ---------------- scratch (device globals; no allocation) ----------------
__device__ int            g_fps[B * S];
__device__ volatile int   g_prog[B];     // fps progress per batch (#indices ready)
__device__ volatile int   g_sync;        // worker pre-phase barrier counter
__device__ float          g_feat[B * N * CP];
__device__ float          g_Wt[CP * D];
__device__ float          g_bias[D];

// ---------------- helpers ----------------
__device__ __forceinline__ unsigned long long pack2(float x, float y) {
    unsigned long long r;
    asm("mov.b64 %0, {%1, %2};" : "=l"(r)
        : "r"(__float_as_uint(x)), "r"(__float_as_uint(y)));
    return r;
}
__device__ __forceinline__ void fma2(unsigned long long &a,
                                     unsigned long long x, unsigned long long y) {
    asm("fma.rn.f32x2 %0, %1, %2, %0;" : "+l"(a) : "l"(x), "l"(y));
}
__device__ __forceinline__ unsigned long long add2(unsigned long long a,
                                                   unsigned long long b) {
    unsigned long long r;
    asm("add.rn.f32x2 %0, %1, %2;" : "=l"(r) : "l"(a), "l"(b));
    return r;
}
__device__ __forceinline__ unsigned long long mul2(unsigned long long a,
                                                   unsigned long long b) {
    unsigned long long r;
    asm("mul.rn.f32x2 %0, %1, %2;" : "=l"(r) : "l"(a), "l"(b));
    return r;
}
__device__ __forceinline__ void unpack2(unsigned long long v, float &x, float &y) {
    unsigned lo, hi;
    asm("mov.b64 {%0, %1}, %2;" : "=r"(lo), "=r"(hi) : "l"(v));
    x = __uint_as_float(lo); y = __uint_as_float(hi);
}
__device__ __forceinline__ unsigned redux_max_u32(unsigned v) {
    unsigned r;
    asm("redux.sync.max.u32 %0, %1, 0xffffffff;" : "=r"(r) : "r"(v));
    return r;
}
__device__ __forceinline__ unsigned redux_min_u32(unsigned v) {
    unsigned r;
    asm("redux.sync.min.u32 %0, %1, 0xffffffff;" : "=r"(r) : "r"(v));
    return r;
}
__device__ __forceinline__ unsigned smem_u32(const void* p) {
    unsigned a;
    asm("{ .reg .u64 t; cvta.to.shared.u64 t, %1; cvt.u32.u64 %0, t; }"
        : "=r"(a) : "l"(p));
    return a;
}
__device__ __forceinline__ unsigned ordenc(float f) {   // order-preserving float->u32
    unsigned b = __float_as_uint(f);
    return ((int)b < 0) ? ~b : (b | 0x80000000u);
}
__device__ __forceinline__ float orddec(unsigned u) {
    return ((int)u < 0) ? __uint_as_float(u & 0x7fffffffu) : __uint_as_float(~u);
}
__device__ __forceinline__ int spread3(int b) {   // 3-bit -> bits 0,3,6
    return (b & 1) | ((b & 2) << 2) | ((b & 4) << 4);
}
__device__ __forceinline__ int morton3(int x, int y, int z) {
    return spread3(x) | (spread3(y) << 1) | (spread3(z) << 2);
}
#define WBAR() asm volatile("bar.sync 1, 256;" ::: "memory")

// ---------------- init: reset cross-CTA state each invocation ----------------
__global__ void init_kernel() {
    if (threadIdx.x < B) g_prog[threadIdx.x] = 0;
    if (threadIdx.x == 0) g_sync = 0;
}

// =======================  FPS (producer): bbox-pruned exact FPS  =================
// 1024 threads, 8 points/thread: halves the hot warp's mandatory update work.
__device__ void fps_block(const float* __restrict__ coor, int b, int tid, float* dsm) {
    const float* base = coor + b * 3 * N;

    // dynamic smem: sort scratch during pre-phase, float4 coord cache in main loop
    float* sx  = dsm;
    float* sy  = dsm + 8192;
    float* sz  = dsm + 16384;
    int*   soi = (int*)(dsm + 24576);
    float4* c4 = (float4*)dsm;           // original-indexed cache (after pre-phase)

    __shared__ int      hist[NCELL];
    __shared__ int      sc[2][NCELL];
    __shared__ unsigned smn[3], smx[3];
    __shared__ unsigned long long sK[2][32];  // packed (distbits<<32)|minidx per warp

    if (tid == 0) {
        g_fps[b * S] = 0;
        __threadfence();
        g_prog[b] = 1;          // group 0 available immediately
    }
    if (tid < 3) { smn[tid] = 0xffffffffu; smx[tid] = 0u; }
    if (tid < NCELL) hist[tid] = 0;
    int lane = tid & 31, wid = tid >> 5;   // 32 warps
    __syncthreads();

    // ---- pre-phase 1: global coord min/max (ordered-uint reduction) ----
    {
        unsigned mnx = 0xffffffffu, mny = 0xffffffffu, mnz = 0xffffffffu;
        unsigned mxx = 0u, mxy = 0u, mxz = 0u;
        for (int j = 0; j < 8; j++) {
            int p = j * TPB + tid;
            unsigned ex = ordenc(base[p]), ey = ordenc(base[N + p]), ez = ordenc(base[2 * N + p]);
            mnx = min(mnx, ex); mny = min(mny, ey); mnz = min(mnz, ez);
            mxx = max(mxx, ex); mxy = max(mxy, ey); mxz = max(mxz, ez);
        }
        mnx = redux_min_u32(mnx); mny = redux_min_u32(mny); mnz = redux_min_u32(mnz);
        mxx = redux_max_u32(mxx); mxy = redux_max_u32(mxy); mxz = redux_max_u32(mxz);
        if (lane == 0) {
            atomicMin(&smn[0], mnx); atomicMin(&smn[1], mny); atomicMin(&smn[2], mnz);
            atomicMax(&smx[0], mxx); atomicMax(&smx[1], mxy); atomicMax(&smx[2], mxz);
        }
    }
    __syncthreads();
    float minx = orddec(smn[0]), miny = orddec(smn[1]), minz = orddec(smn[2]);
    float sclx = 8.0f / fmaxf(orddec(smx[0]) - minx, 1e-9f);
    float scly = 8.0f / fmaxf(orddec(smx[1]) - miny, 1e-9f);
    float sclz = 8.0f / fmaxf(orddec(smx[2]) - minz, 1e-9f);

    // ---- pre-phase 2: counting sort by Morton cell (compact warp regions) ----
    for (int j = 0; j < 8; j++) {
        int p = j * TPB + tid;
        int ix = min(7, max(0, (int)((base[p]         - minx) * sclx)));
        int iy = min(7, max(0, (int)((base[N + p]     - miny) * scly)));
        int iz = min(7, max(0, (int)((base[2 * N + p] - minz) * sclz)));
        atomicAdd(&hist[morton3(ix, iy, iz)], 1);
    }
    __syncthreads();
    // exclusive scan over 512 cells (Hillis-Steele; first 512 threads participate)
    if (tid < NCELL) sc[0][tid] = hist[tid];
    __syncthreads();
    int src = 0;
    for (int off = 1; off < NCELL; off <<= 1) {
        if (tid < NCELL) {
            int v = sc[src][tid];
            if (tid >= off) v += sc[src][tid - off];
            sc[src ^ 1][tid] = v;
        }
        __syncthreads();
        src ^= 1;
    }
    if (tid < NCELL) hist[tid] = (tid == 0) ? 0 : sc[src][tid - 1];  // running offsets
    __syncthreads();
    for (int j = 0; j < 8; j++) {
        int p = j * TPB + tid;
        float x = base[p], y = base[N + p], z = base[2 * N + p];
        int ix = min(7, max(0, (int)((x - minx) * sclx)));
        int iy = min(7, max(0, (int)((y - miny) * scly)));
        int iz = min(7, max(0, (int)((z - minz) * sclz)));
        int pos = atomicAdd(&hist[morton3(ix, iy, iz)], 1);
        sx[pos] = x; sy[pos] = y; sz[pos] = z; soi[pos] = p;
    }
    __syncthreads();

    // ---- load my 8 sorted points + bbox into registers ----
    unsigned long long px2[4], py2[4], pz2[4];
    float dist[8];
    unsigned oic[8];             // 8191 - original_index (key low field, precomputed)
    float lox = 1e30f, hix = -1e30f, loy = 1e30f, hiy = -1e30f, loz = 1e30f, hiz = -1e30f;
    int b8 = tid * 8;
#pragma unroll
    for (int q = 0; q < 4; q++) {
        float x0 = sx[b8 + 2 * q], x1 = sx[b8 + 2 * q + 1];
        float y0 = sy[b8 + 2 * q], y1 = sy[b8 + 2 * q + 1];
        float z0 = sz[b8 + 2 * q], z1 = sz[b8 + 2 * q + 1];
        px2[q] = pack2(x0, x1); py2[q] = pack2(y0, y1); pz2[q] = pack2(z0, z1);
        lox = fminf(lox, fminf(x0, x1)); hix = fmaxf(hix, fmaxf(x0, x1));
        loy = fminf(loy, fminf(y0, y1)); hiy = fmaxf(hiy, fmaxf(y0, y1));
        loz = fminf(loz, fminf(z0, z1)); hiz = fmaxf(hiz, fmaxf(z0, z1));
    }
    unsigned mxo = 0u;
#pragma unroll
    for (int j = 0; j < 8; j++) {
        dist[j] = 1e10f;
        oic[j] = (unsigned)(8191 - soi[b8 + j]);
        mxo = max(mxo, oic[j]);
    }
    float bval = 1e10f;
    int   bidx = 8191 - (int)mxo;  // all dists tie at 1e10 -> min orig idx of my 8

    float cx = base[0], cy = base[N], cz = base[2 * N];
    __syncthreads();

    // ---- repurpose dsm as ORIGINAL-indexed float4 coord cache (1 LDS.128/step) ----
    for (int j = tid; j < N; j += TPB) {
        float4 v;
        v.x = base[j]; v.y = base[N + j]; v.z = base[2 * N + j]; v.w = 0.f;
        c4[j] = v;
    }
    __syncthreads();

    // ---- main loop ----
    for (int s = 1; s < S; s++) {
        // sound skip test: dbox2 <= |p-c|^2 for every owned point (monotone rounding)
        float ddx = fmaxf(fmaxf(lox - cx, cx - hix), 0.f);
        float ddy = fmaxf(fmaxf(loy - cy, cy - hiy), 0.f);
        float ddz = fmaxf(fmaxf(loz - cz, cz - hiz), 0.f);
        float dbox2 = ddx * ddx;
        dbox2 = fmaf(ddy, ddy, dbox2);
        dbox2 = fmaf(ddz, ddz, dbox2);

        if (dbox2 < bval) {
            unsigned long long ncx = pack2(-cx, -cx);
            unsigned long long ncy = pack2(-cy, -cy);
            unsigned long long ncz = pack2(-cz, -cz);
            // packed update: (p + (-c)) == (p - c); mul2/fma2/fma2 == scalar chain
#pragma unroll
            for (int q = 0; q < 4; q++) {
                unsigned long long dx = add2(px2[q], ncx);
                unsigned long long dy = add2(py2[q], ncy);
                unsigned long long dz = add2(pz2[q], ncz);
                unsigned long long d2 = mul2(dx, dx);
                fma2(d2, dy, dy);
                fma2(d2, dz, dz);
                float dlo, dhi; unpack2(d2, dlo, dhi);
                dist[2 * q]     = fminf(dist[2 * q],     dlo);
                dist[2 * q + 1] = fminf(dist[2 * q + 1], dhi);
            }
            // exact local argmax via u64 key tree: (dist_bits << 32) | (8191 - oidx)
            // max key == max dist, tie -> min original index
            unsigned long long kk[4];
#pragma unroll
            for (int j = 0; j < 4; j++) {
                unsigned long long k0 =
                    ((unsigned long long)__float_as_uint(dist[2 * j]) << 32) | oic[2 * j];
                unsigned long long k1 =
                    ((unsigned long long)__float_as_uint(dist[2 * j + 1]) << 32) | oic[2 * j + 1];
                kk[j] = k0 > k1 ? k0 : k1;
            }
            kk[0] = kk[0] > kk[1] ? kk[0] : kk[1];
            kk[2] = kk[2] > kk[3] ? kk[2] : kk[3];
            kk[0] = kk[0] > kk[2] ? kk[0] : kk[2];
            bval = __uint_as_float((unsigned)(kk[0] >> 32));
            bidx = 8191 - (int)(kk[0] & 0x3fffull);
        }

        // warp stage: max dist bits, then min orig index among ties (exact)
        unsigned db = __float_as_uint(bval);   // d >= 0: bit order == float order
        unsigned mb = redux_max_u32(db);
        unsigned cand = (db == mb) ? (unsigned)bidx : 0xffffffffu;
        unsigned im = redux_min_u32(cand);
        int buf = s & 1;
        if (lane == 0)
            sK[buf][wid] = ((unsigned long long)mb << 32) | im;
        __syncthreads();
        // block stage: every warp reduces all 32 slots (one per warp, no pads)
        unsigned long long kw = sK[buf][lane];
        unsigned m2s = (unsigned)(kw >> 32);
        unsigned i2s = (unsigned)kw;
        unsigned MB = redux_max_u32(m2s);
        unsigned c2 = (m2s == MB) ? i2s : 0xffffffffu;
        unsigned I = redux_min_u32(c2);
        if (tid == 0) {
            g_fps[b * S + s] = (int)I;
            if ((s & 15) == 15) {      // batched publish (s=2047 -> prog=2048)
                __threadfence();
                g_prog[b] = s + 1;
            }
        }
        float4 cv = c4[I];             // single broadcast LDS.128
        cx = cv.x; cy = cv.y; cz = cv.z;
    }
}

// =======================  worker (consumer) path  =======================
__device__ void worker_block(const float* __restrict__ coor, const float* __restrict__ fea,
                             const float* __restrict__ W, const float* __restrict__ bb,
                             const float* __restrict__ gamma, const float* __restrict__ beta,
                             const float* __restrict__ mean, const float* __restrict__ var,
                             float* __restrict__ out_coor, float* __restrict__ out_fea,
                             float* smem, int widx, int tid) {
    // ---- pre-phase: fold (worker 0) + feat build (all workers, 1024 thr) ----
    if (widx == 0 && tid < 256) {
        int d = tid;
        float sc = gamma[d] * rsqrtf(var[d] + 1e-5f);
        for (int c = 0; c < 128; c++)
            g_Wt[c * D + d] = W[d * 131 + c] * sc;
        for (int c = 128; c < 131; c++)
            g_Wt[c * D + d] = W[d * 131 + c] * sc * 10.0f;
        g_Wt[131 * D + d] = 0.f;
        g_bias[d] = (bb[d] - mean[d]) * sc + beta[d];
    }
    for (int i = widx * TPB + tid; i < B * N * CP; i += NWORK * TPB) {
        int c = i % CP;
        int bn = i / CP;
        int n = bn % N;
        int b = bn / N;
        float v;
        if (c < C)        v = fea[(b * C + c) * N + n];
        else if (c < 131) v = coor[(b * 3 + (c - C)) * N + n];
        else              v = 0.f;
        g_feat[i] = v;
    }
    __syncthreads();
    if (tid == 0) {
        __threadfence();
        atomicAdd((int*)&g_sync, 1);
        while (g_sync < NWORK) __nanosleep(128);
    }
    __syncthreads();
    __threadfence();
    if (tid >= 256) return;        // main loop uses 256 threads + named bars

    // ---- smem layout ----
    float* Wsh = smem;             // CP*D
    float* gsh = smem + CP * D;    // CP*K
    float* red = gsh + CP * K;     // 4*D
    __shared__ int   s_cnt;
    __shared__ float s_cd[CAP];
    __shared__ int   s_cidx[CAP];
    __shared__ int   s_sel[32];
    __shared__ int   s_nidx[32];
    __shared__ float s_cc[3];
    __shared__ int   s_ci;

    for (int i = tid; i < CP * D; i += 256) Wsh[i] = g_Wt[i];
    float biasv = g_bias[tid];

    unsigned sbase = smem_u32(smem);
    int dt = tid & 63, kt = tid >> 6;
    unsigned waddr0 = sbase + (unsigned)(dt * 16);
    const float* gb = gsh + kt * 8;
    WBAR();

    for (int i = widx; i < B * S; i += NWORK) {
        int s = i >> 2, b = i & 3;          // (s,b) order tracks the fps frontier
        const float* base = coor + b * 3 * N;

        if (tid == 0) {
            while (g_prog[b] <= s) __nanosleep(64);
            __threadfence();
            s_ci = __ldcg(&g_fps[b * S + s]);
            s_cnt = 0;
        }
        WBAR();
        int ci = s_ci;
        float cx = __ldg(base + ci), cy = __ldg(base + N + ci), cz = __ldg(base + 2 * N + ci);
        if (tid < 3) {
            float v = (tid == 0) ? cx : (tid == 1) ? cy : cz;
            out_coor[(b * 3 + tid) * S + s] = v;
            s_cc[tid] = v;
        }
        float cc2 = cx * cx + cy * cy + cz * cz;

        // radius scan (expanded form matches reference)
        for (int p = tid; p < N; p += 256) {
            float x = base[p], y = base[N + p], z = base[2 * N + p];
            float pp = x * x + y * y + z * z;
            float dt2 = cx * x + cy * y + cz * z;
            float sq = cc2 + pp - 2.f * dt2;
            if (sq <= R2) {
                int pos = atomicAdd(&s_cnt, 1);
                if (pos < CAP) { s_cd[pos] = sq; s_cidx[pos] = p; }
            }
        }
        WBAR();
        int n = min(s_cnt, CAP);
        for (int c = tid; c < n; c += 256) {
            float dc = s_cd[c]; int ic = s_cidx[c];
            int r = 0;
            for (int j = 0; j < n; j++) {
                float dj = s_cd[j]; int ij = s_cidx[j];
                r += (dj < dc) || (dj == dc && ij < ic);
            }
            if (r < 32) s_sel[r] = ic;
        }
        WBAR();
        if (tid < 32) {
            int m = min(n, 32);
            s_nidx[tid] = (tid < m) ? s_sel[tid] : s_sel[0];
        }
        WBAR();

        // gather 32 neighbors x 132 channels (pure float4 copy)
        for (int q = tid; q < 32 * 33; q += 256) {
            int k = q & 31, cq = q >> 5;
            const float4 v = *(const float4*)(g_feat + (size_t)(b * N + s_nidx[k]) * CP + cq * 4);
            int c = cq * 4;
            gsh[(c + 0) * 32 + k] = v.x;
            gsh[(c + 1) * 32 + k] = v.y;
            gsh[(c + 2) * 32 + k] = v.z;
            gsh[(c + 3) * 32 + k] = v.w;
        }
        WBAR();

        unsigned long long acc[16];
#pragma unroll
        for (int q = 0; q < 16; q++) acc[q] = 0ull;
#pragma unroll 2
        for (int c = 0; c < CP; c++) {
            unsigned long long w0, w1;
            unsigned a0 = waddr0 + (unsigned)(c * (D * 4));
            asm volatile("ld.shared.v2.b64 {%0,%1}, [%2];" : "=l"(w0), "=l"(w1) : "r"(a0));
            float4 ga = *(const float4*)(gb + c * 32);
            float4 gc = *(const float4*)(gb + c * 32 + 4);
            unsigned long long g0 = pack2(ga.x, ga.x), g1 = pack2(ga.y, ga.y);
            unsigned long long g2 = pack2(ga.z, ga.z), g3 = pack2(ga.w, ga.w);
            unsigned long long g4 = pack2(gc.x, gc.x), g5 = pack2(gc.y, gc.y);
            unsigned long long g6 = pack2(gc.z, gc.z), g7 = pack2(gc.w, gc.w);
            fma2(acc[0],  g0, w0); fma2(acc[1],  g0, w1);
            fma2(acc[2],  g1, w0); fma2(acc[3],  g1, w1);
            fma2(acc[4],  g2, w0); fma2(acc[5],  g2, w1);
            fma2(acc[6],  g3, w0); fma2(acc[7],  g3, w1);
            fma2(acc[8],  g4, w0); fma2(acc[9],  g4, w1);
            fma2(acc[10], g5, w0); fma2(acc[11], g5, w1);
            fma2(acc[12], g6, w0); fma2(acc[13], g6, w1);
            fma2(acc[14], g7, w0); fma2(acc[15], g7, w1);
        }

        float mx[4];
#pragma unroll
        for (int l = 0; l < 4; l++) mx[l] = -1e30f;
#pragma unroll
        for (int ki = 0; ki < 8; ki++) {
            float a, bv;
            unpack2(acc[ki * 2 + 0], a, bv);
            mx[0] = fmaxf(mx[0], a); mx[1] = fmaxf(mx[1], bv);
            unpack2(acc[ki * 2 + 1], a, bv);
            mx[2] = fmaxf(mx[2], a); mx[3] = fmaxf(mx[3], bv);
        }
#pragma unroll
        for (int l = 0; l < 4; l++)
            red[kt * D + dt * 4 + l] = mx[l];
        WBAR();
        {
            float v = red[tid];
#pragma unroll
            for (int q = 1; q < 4; q++) v = fmaxf(v, red[q * D + tid]);
            float adj = Wsh[128 * D + tid] * s_cc[0]
                      + Wsh[129 * D + tid] * s_cc[1]
                      + Wsh[130 * D + tid] * s_cc[2];
            float o = v - adj + biasv;
            o = o > 0.f ? o : 0.f;
            out_fea[((size_t)b * D + tid) * S + s] = o;
        }
        WBAR();
    }
}

// =======================  fused persistent kernel  ======================
__global__ void __launch_bounds__(TPB, 1) fused_kernel(
    const float* __restrict__ coor, const float* __restrict__ fea,
    const float* __restrict__ W, const float* __restrict__ bb,
    const float* __restrict__ gamma, const float* __restrict__ beta,
    const float* __restrict__ mean, const float* __restrict__ var,
    float* __restrict__ out_coor, float* __restrict__ out_fea) {
    extern __shared__ float smem[];
    int cta = blockIdx.x, tid = threadIdx.x;
    if (cta < NFPS) {
        fps_block(coor, cta, tid, smem);
    } else {
        worker_block(coor, fea, W, bb, gamma, beta, mean, var,
                     out_coor, out_fea, smem, cta - NFPS, tid);
    }
}

// ---------------- launch ----------------
extern "C" void kernel_launch(void* const* d_in, const int* in_sizes, int n_in,
                              void* d_out, int out_size) {
    const float* coor  = (const float*)d_in[0];
    const float* fea   = (const float*)d_in[1];
    const float* W     = (const float*)d_in[2];
    const float* bb    = (const float*)d_in[3];
    const float* gamma = (const float*)d_in[4];
    const float* beta  = (const float*)d_in[5];
    const float* mean  = (const float*)d_in[6];
    const float* var   = (const float*)d_in[7];

    float* out      = (float*)d_out;
    float* out_coor = out;              // (B,3,S)
    float* out_fea  = out + B * 3 * S;  // (B,2C,S)

    init_kernel<<<1, 32>>>();

    const int smem_bytes = (CP * D + CP * K + 4 * D) * 4;  // 156160 B (fps needs 131072)
    cudaFuncSetAttribute(fused_kernel, cudaFuncAttributeMaxDynamicSharedMemorySize, smem_bytes);
    fused_kernel<<<NCTA, TPB, smem_bytes>>>(coor, fea, W, bb, gamma, beta,
                                            mean, var, out_coor, out_fea);
}

// round 16
// speedup vs baseline: 1.3132x; 1.3132x over previous
#include <cuda_runtime.h>

#define B 4
#define N 8192
#define C 128
#define S 2048
#define K 32
#define D 256      // 2C
#define CP 132     // C+3 padded
#define R2 0.01f
#define CAP 256
#define NFPS 4
#define NWORK 144
#define NCTA 148
#define NCELL 512  // 8x8x8 grid

// ---------------- scratch (device globals; no allocation) ----------------
__device__ int            g_fps[B * S];
__device__ volatile int   g_prog[B];     // fps progress per batch (#indices ready)
__device__ volatile int   g_sync;        // worker pre-phase barrier counter
__device__ float          g_feat[B * N * CP];
__device__ float          g_Wt[CP * D];
__device__ float          g_bias[D];

// ---------------- helpers ----------------
__device__ __forceinline__ unsigned long long pack2(float x, float y) {
    unsigned long long r;
    asm("mov.b64 %0, {%1, %2};" : "=l"(r)
        : "r"(__float_as_uint(x)), "r"(__float_as_uint(y)));
    return r;
}
__device__ __forceinline__ void fma2(unsigned long long &a,
                                     unsigned long long x, unsigned long long y) {
    asm("fma.rn.f32x2 %0, %1, %2, %0;" : "+l"(a) : "l"(x), "l"(y));
}
__device__ __forceinline__ unsigned long long add2(unsigned long long a,
                                                   unsigned long long b) {
    unsigned long long r;
    asm("add.rn.f32x2 %0, %1, %2;" : "=l"(r) : "l"(a), "l"(b));
    return r;
}
__device__ __forceinline__ unsigned long long mul2(unsigned long long a,
                                                   unsigned long long b) {
    unsigned long long r;
    asm("mul.rn.f32x2 %0, %1, %2;" : "=l"(r) : "l"(a), "l"(b));
    return r;
}
__device__ __forceinline__ void unpack2(unsigned long long v, float &x, float &y) {
    unsigned lo, hi;
    asm("mov.b64 {%0, %1}, %2;" : "=r"(lo), "=r"(hi) : "l"(v));
    x = __uint_as_float(lo); y = __uint_as_float(hi);
}
__device__ __forceinline__ unsigned redux_max_u32(unsigned v) {
    unsigned r;
    asm("redux.sync.max.u32 %0, %1, 0xffffffff;" : "=r"(r) : "r"(v));
    return r;
}
__device__ __forceinline__ unsigned redux_min_u32(unsigned v) {
    unsigned r;
    asm("redux.sync.min.u32 %0, %1, 0xffffffff;" : "=r"(r) : "r"(v));
    return r;
}
__device__ __forceinline__ unsigned smem_u32(const void* p) {
    unsigned a;
    asm("{ .reg .u64 t; cvta.to.shared.u64 t, %1; cvt.u32.u64 %0, t; }"
        : "=r"(a) : "l"(p));
    return a;
}
__device__ __forceinline__ unsigned ordenc(float f) {   // order-preserving float->u32
    unsigned b = __float_as_uint(f);
    return ((int)b < 0) ? ~b : (b | 0x80000000u);
}
__device__ __forceinline__ float orddec(unsigned u) {
    return ((int)u < 0) ? __uint_as_float(u & 0x7fffffffu) : __uint_as_float(~u);
}
__device__ __forceinline__ int spread3(int b) {   // 3-bit -> bits 0,3,6
    return (b & 1) | ((b & 2) << 2) | ((b & 4) << 4);
}
__device__ __forceinline__ int morton3(int x, int y, int z) {
    return spread3(x) | (spread3(y) << 1) | (spread3(z) << 2);
}
#define WBAR() asm volatile("bar.sync 1, 256;" ::: "memory")

// ---------------- init: reset cross-CTA state each invocation ----------------
__global__ void init_kernel() {
    if (threadIdx.x < B) g_prog[threadIdx.x] = 0;
    if (threadIdx.x == 0) g_sync = 0;
}

// =======================  FPS (producer): bbox-pruned exact FPS  =================
__device__ void fps_block(const float* __restrict__ coor, int b, int tid, float* dsm) {
    const float* base = coor + b * 3 * N;

    // dynamic smem: sort scratch during pre-phase, float4 coord cache in main loop
    float* sx  = dsm;
    float* sy  = dsm + 8192;
    float* sz  = dsm + 16384;
    int*   soi = (int*)(dsm + 24576);
    float4* c4 = (float4*)dsm;           // original-indexed cache (after pre-phase)

    __shared__ int      hist[NCELL];
    __shared__ int      sc[2][NCELL];
    __shared__ unsigned smn[3], smx[3];
    __shared__ unsigned long long sK[2][32];  // packed (distbits<<32)|minidx per warp

    if (tid == 0) {
        g_fps[b * S] = 0;
        __threadfence();
        g_prog[b] = 1;          // group 0 available immediately
    }
    if (tid < 3) { smn[tid] = 0xffffffffu; smx[tid] = 0u; }
    hist[tid] = 0;
    if (tid < 32) {             // pad slots: dist bits 0, idx 0xffffffff (never win)
        sK[0][tid] = 0x00000000ffffffffull;
        sK[1][tid] = 0x00000000ffffffffull;
    }
    int lane = tid & 31, wid = tid >> 5;
    __syncthreads();

    // ---- pre-phase 1: global coord min/max (ordered-uint reduction) ----
    {
        unsigned mnx = 0xffffffffu, mny = 0xffffffffu, mnz = 0xffffffffu;
        unsigned mxx = 0u, mxy = 0u, mxz = 0u;
        for (int j = 0; j < 16; j++) {
            int p = j * 512 + tid;
            unsigned ex = ordenc(base[p]), ey = ordenc(base[N + p]), ez = ordenc(base[2 * N + p]);
            mnx = min(mnx, ex); mny = min(mny, ey); mnz = min(mnz, ez);
            mxx = max(mxx, ex); mxy = max(mxy, ey); mxz = max(mxz, ez);
        }
        mnx = redux_min_u32(mnx); mny = redux_min_u32(mny); mnz = redux_min_u32(mnz);
        mxx = redux_max_u32(mxx); mxy = redux_max_u32(mxy); mxz = redux_max_u32(mxz);
        if (lane == 0) {
            atomicMin(&smn[0], mnx); atomicMin(&smn[1], mny); atomicMin(&smn[2], mnz);
            atomicMax(&smx[0], mxx); atomicMax(&smx[1], mxy); atomicMax(&smx[2], mxz);
        }
    }
    __syncthreads();
    float minx = orddec(smn[0]), miny = orddec(smn[1]), minz = orddec(smn[2]);
    float sclx = 8.0f / fmaxf(orddec(smx[0]) - minx, 1e-9f);
    float scly = 8.0f / fmaxf(orddec(smx[1]) - miny, 1e-9f);
    float sclz = 8.0f / fmaxf(orddec(smx[2]) - minz, 1e-9f);

    // ---- pre-phase 2: counting sort by Morton cell (compact warp regions) ----
    for (int j = 0; j < 16; j++) {
        int p = j * 512 + tid;
        int ix = min(7, max(0, (int)((base[p]         - minx) * sclx)));
        int iy = min(7, max(0, (int)((base[N + p]     - miny) * scly)));
        int iz = min(7, max(0, (int)((base[2 * N + p] - minz) * sclz)));
        atomicAdd(&hist[morton3(ix, iy, iz)], 1);
    }
    __syncthreads();
    // exclusive scan over 512 cells (Hillis-Steele, 512 threads)
    sc[0][tid] = hist[tid];
    __syncthreads();
    int src = 0;
    for (int off = 1; off < NCELL; off <<= 1) {
        int v = sc[src][tid];
        if (tid >= off) v += sc[src][tid - off];
        sc[src ^ 1][tid] = v;
        __syncthreads();
        src ^= 1;
    }
    hist[tid] = (tid == 0) ? 0 : sc[src][tid - 1];   // running offsets
    __syncthreads();
    for (int j = 0; j < 16; j++) {
        int p = j * 512 + tid;
        float x = base[p], y = base[N + p], z = base[2 * N + p];
        int ix = min(7, max(0, (int)((x - minx) * sclx)));
        int iy = min(7, max(0, (int)((y - miny) * scly)));
        int iz = min(7, max(0, (int)((z - minz) * sclz)));
        int pos = atomicAdd(&hist[morton3(ix, iy, iz)], 1);
        sx[pos] = x; sy[pos] = y; sz[pos] = z; soi[pos] = p;
    }
    __syncthreads();

    // ---- load my 16 sorted points + bbox into registers ----
    unsigned long long px2[8], py2[8], pz2[8];
    float dist[16];
    unsigned oic[16];            // 8191 - original_index (key low field, precomputed)
    float lox = 1e30f, hix = -1e30f, loy = 1e30f, hiy = -1e30f, loz = 1e30f, hiz = -1e30f;
    int b16 = tid * 16;
#pragma unroll
    for (int q = 0; q < 8; q++) {
        float x0 = sx[b16 + 2 * q], x1 = sx[b16 + 2 * q + 1];
        float y0 = sy[b16 + 2 * q], y1 = sy[b16 + 2 * q + 1];
        float z0 = sz[b16 + 2 * q], z1 = sz[b16 + 2 * q + 1];
        px2[q] = pack2(x0, x1); py2[q] = pack2(y0, y1); pz2[q] = pack2(z0, z1);
        lox = fminf(lox, fminf(x0, x1)); hix = fmaxf(hix, fmaxf(x0, x1));
        loy = fminf(loy, fminf(y0, y1)); hiy = fmaxf(hiy, fmaxf(y0, y1));
        loz = fminf(loz, fminf(z0, z1)); hiz = fmaxf(hiz, fmaxf(z0, z1));
    }
#pragma unroll
    for (int j = 0; j < 16; j++) {
        dist[j] = 1e10f;
        oic[j] = (unsigned)(8191 - soi[b16 + j]);
    }
    float bval = 1e10f;
    int   bidx = 0;           // rebuilt on first update (step 1 updates all)

    float cx = base[0], cy = base[N], cz = base[2 * N];
    __syncthreads();

    // ---- repurpose dsm as ORIGINAL-indexed float4 coord cache (1 LDS.128/step) ----
    for (int j = tid; j < N; j += 512) {
        float4 v;
        v.x = base[j]; v.y = base[N + j]; v.z = base[2 * N + j]; v.w = 0.f;
        c4[j] = v;
    }
    __syncthreads();

    // ---- main loop ----
    for (int s = 1; s < S; s++) {
        // sound skip test: dbox2 <= |p-c|^2 for every owned point (monotone rounding)
        float ddx = fmaxf(fmaxf(lox - cx, cx - hix), 0.f);
        float ddy = fmaxf(fmaxf(loy - cy, cy - hiy), 0.f);
        float ddz = fmaxf(fmaxf(loz - cz, cz - hiz), 0.f);
        float dbox2 = ddx * ddx;
        dbox2 = fmaf(ddy, ddy, dbox2);
        dbox2 = fmaf(ddz, ddz, dbox2);

        if (dbox2 < bval) {
            unsigned long long ncx = pack2(-cx, -cx);
            unsigned long long ncy = pack2(-cy, -cy);
            unsigned long long ncz = pack2(-cz, -cz);
            // packed update: (p + (-c)) == (p - c); mul2/fma2/fma2 == scalar chain
#pragma unroll
            for (int q = 0; q < 8; q++) {
                unsigned long long dx = add2(px2[q], ncx);
                unsigned long long dy = add2(py2[q], ncy);
                unsigned long long dz = add2(pz2[q], ncz);
                unsigned long long d2 = mul2(dx, dx);
                fma2(d2, dy, dy);
                fma2(d2, dz, dz);
                float dlo, dhi; unpack2(d2, dlo, dhi);
                dist[2 * q]     = fminf(dist[2 * q],     dlo);
                dist[2 * q + 1] = fminf(dist[2 * q + 1], dhi);
            }
            // exact local argmax via u64 key tree: (dist_bits << 32) | (8191 - oidx)
            // max key == max dist, tie -> min original index
            unsigned long long kk[8];
#pragma unroll
            for (int j = 0; j < 8; j++) {
                unsigned long long k0 =
                    ((unsigned long long)__float_as_uint(dist[2 * j]) << 32) | oic[2 * j];
                unsigned long long k1 =
                    ((unsigned long long)__float_as_uint(dist[2 * j + 1]) << 32) | oic[2 * j + 1];
                kk[j] = k0 > k1 ? k0 : k1;
            }
#pragma unroll
            for (int j = 0; j < 4; j++) kk[j] = kk[j] > kk[j + 4] ? kk[j] : kk[j + 4];
            kk[0] = kk[0] > kk[1] ? kk[0] : kk[1];
            kk[2] = kk[2] > kk[3] ? kk[2] : kk[3];
            kk[0] = kk[0] > kk[2] ? kk[0] : kk[2];
            bval = __uint_as_float((unsigned)(kk[0] >> 32));
            bidx = 8191 - (int)(kk[0] & 0x3fffull);
        }

        // warp stage: max dist bits, then min orig index among ties (exact)
        unsigned db = __float_as_uint(bval);   // d >= 0: bit order == float order
        unsigned mb = redux_max_u32(db);
        unsigned cand = (db == mb) ? (unsigned)bidx : 0xffffffffu;
        unsigned im = redux_min_u32(cand);
        int buf = s & 1;
        if (lane == 0)
            sK[buf][wid] = ((unsigned long long)mb << 32) | im;
        __syncthreads();
        // block stage: every warp reduces all 32 slots (pads lose)
        unsigned long long kw = sK[buf][lane];
        unsigned m2s = (unsigned)(kw >> 32);
        unsigned i2s = (unsigned)kw;
        unsigned MB = redux_max_u32(m2s);
        unsigned c2 = (m2s == MB) ? i2s : 0xffffffffu;
        unsigned I = redux_min_u32(c2);
        if (tid == 0) {
            g_fps[b * S + s] = (int)I;
            if ((s & 15) == 15) {      // batched publish (s=2047 -> prog=2048)
                __threadfence();
                g_prog[b] = s + 1;
            }
        }
        float4 cv = c4[I];             // single broadcast LDS.128
        cx = cv.x; cy = cv.y; cz = cv.z;
    }
}

// =======================  worker (consumer) path  =======================
__device__ void worker_block(const float* __restrict__ coor, const float* __restrict__ fea,
                             const float* __restrict__ W, const float* __restrict__ bb,
                             const float* __restrict__ gamma, const float* __restrict__ beta,
                             const float* __restrict__ mean, const float* __restrict__ var,
                             float* __restrict__ out_coor, float* __restrict__ out_fea,
                             float* smem, int widx, int tid) {
    // ---- pre-phase: fold (worker 0) + feat build (all workers, 512 thr) ----
    if (widx == 0 && tid < 256) {
        int d = tid;
        float sc = gamma[d] * rsqrtf(var[d] + 1e-5f);
        for (int c = 0; c < 128; c++)
            g_Wt[c * D + d] = W[d * 131 + c] * sc;
        for (int c = 128; c < 131; c++)
            g_Wt[c * D + d] = W[d * 131 + c] * sc * 10.0f;
        g_Wt[131 * D + d] = 0.f;
        g_bias[d] = (bb[d] - mean[d]) * sc + beta[d];
    }
    for (int i = widx * 512 + tid; i < B * N * CP; i += NWORK * 512) {
        int c = i % CP;
        int bn = i / CP;
        int n = bn % N;
        int b = bn / N;
        float v;
        if (c < C)        v = fea[(b * C + c) * N + n];
        else if (c < 131) v = coor[(b * 3 + (c - C)) * N + n];
        else              v = 0.f;
        g_feat[i] = v;
    }
    __syncthreads();
    if (tid == 0) {
        __threadfence();
        atomicAdd((int*)&g_sync, 1);
        while (g_sync < NWORK) __nanosleep(128);
    }
    __syncthreads();
    __threadfence();
    if (tid >= 256) return;        // main loop uses 256 threads + named bars

    // ---- smem layout ----
    float* Wsh = smem;             // CP*D
    float* gsh = smem + CP * D;    // CP*K
    float* red = gsh + CP * K;     // 4*D
    __shared__ int   s_cnt;
    __shared__ float s_cd[CAP];
    __shared__ int   s_cidx[CAP];
    __shared__ int   s_sel[32];
    __shared__ int   s_nidx[32];
    __shared__ float s_cc[3];
    __shared__ int   s_ci;

    for (int i = tid; i < CP * D; i += 256) Wsh[i] = g_Wt[i];
    float biasv = g_bias[tid];

    unsigned sbase = smem_u32(smem);
    int dt = tid & 63, kt = tid >> 6;
    unsigned waddr0 = sbase + (unsigned)(dt * 16);
    const float* gb = gsh + kt * 8;
    WBAR();

    for (int i = widx; i < B * S; i += NWORK) {
        int s = i >> 2, b = i & 3;          // (s,b) order tracks the fps frontier
        const float* base = coor + b * 3 * N;

        if (tid == 0) {
            while (g_prog[b] <= s) __nanosleep(64);
            __threadfence();
            s_ci = __ldcg(&g_fps[b * S + s]);
            s_cnt = 0;
        }
        WBAR();
        int ci = s_ci;
        float cx = __ldg(base + ci), cy = __ldg(base + N + ci), cz = __ldg(base + 2 * N + ci);
        if (tid < 3) {
            float v = (tid == 0) ? cx : (tid == 1) ? cy : cz;
            out_coor[(b * 3 + tid) * S + s] = v;
            s_cc[tid] = v;
        }
        float cc2 = cx * cx + cy * cy + cz * cz;

        // radius scan (expanded form matches reference)
        for (int p = tid; p < N; p += 256) {
            float x = base[p], y = base[N + p], z = base[2 * N + p];
            float pp = x * x + y * y + z * z;
            float dt2 = cx * x + cy * y + cz * z;
            float sq = cc2 + pp - 2.f * dt2;
            if (sq <= R2) {
                int pos = atomicAdd(&s_cnt, 1);
                if (pos < CAP) { s_cd[pos] = sq; s_cidx[pos] = p; }
            }
        }
        WBAR();
        int n = min(s_cnt, CAP);
        for (int c = tid; c < n; c += 256) {
            float dc = s_cd[c]; int ic = s_cidx[c];
            int r = 0;
            for (int j = 0; j < n; j++) {
                float dj = s_cd[j]; int ij = s_cidx[j];
                r += (dj < dc) || (dj == dc && ij < ic);
            }
            if (r < 32) s_sel[r] = ic;
        }
        WBAR();
        if (tid < 32) {
            int m = min(n, 32);
            s_nidx[tid] = (tid < m) ? s_sel[tid] : s_sel[0];
        }
        WBAR();

        // gather 32 neighbors x 132 channels (pure float4 copy)
        for (int q = tid; q < 32 * 33; q += 256) {
            int k = q & 31, cq = q >> 5;
            const float4 v = *(const float4*)(g_feat + (size_t)(b * N + s_nidx[k]) * CP + cq * 4);
            int c = cq * 4;
            gsh[(c + 0) * 32 + k] = v.x;
            gsh[(c + 1) * 32 + k] = v.y;
            gsh[(c + 2) * 32 + k] = v.z;
            gsh[(c + 3) * 32 + k] = v.w;
        }
        WBAR();

        unsigned long long acc[16];
#pragma unroll
        for (int q = 0; q < 16; q++) acc[q] = 0ull;
#pragma unroll 2
        for (int c = 0; c < CP; c++) {
            unsigned long long w0, w1;
            unsigned a0 = waddr0 + (unsigned)(c * (D * 4));
            asm volatile("ld.shared.v2.b64 {%0,%1}, [%2];" : "=l"(w0), "=l"(w1) : "r"(a0));
            float4 ga = *(const float4*)(gb + c * 32);
            float4 gc = *(const float4*)(gb + c * 32 + 4);
            unsigned long long g0 = pack2(ga.x, ga.x), g1 = pack2(ga.y, ga.y);
            unsigned long long g2 = pack2(ga.z, ga.z), g3 = pack2(ga.w, ga.w);
            unsigned long long g4 = pack2(gc.x, gc.x), g5 = pack2(gc.y, gc.y);
            unsigned long long g6 = pack2(gc.z, gc.z), g7 = pack2(gc.w, gc.w);
            fma2(acc[0],  g0, w0); fma2(acc[1],  g0, w1);
            fma2(acc[2],  g1, w0); fma2(acc[3],  g1, w1);
            fma2(acc[4],  g2, w0); fma2(acc[5],  g2, w1);
            fma2(acc[6],  g3, w0); fma2(acc[7],  g3, w1);
            fma2(acc[8],  g4, w0); fma2(acc[9],  g4, w1);
            fma2(acc[10], g5, w0); fma2(acc[11], g5, w1);
            fma2(acc[12], g6, w0); fma2(acc[13], g6, w1);
            fma2(acc[14], g7, w0); fma2(acc[15], g7, w1);
        }

        float mx[4];
#pragma unroll
        for (int l = 0; l < 4; l++) mx[l] = -1e30f;
#pragma unroll
        for (int ki = 0; ki < 8; ki++) {
            float a, bv;
            unpack2(acc[ki * 2 + 0], a, bv);
            mx[0] = fmaxf(mx[0], a); mx[1] = fmaxf(mx[1], bv);
            unpack2(acc[ki * 2 + 1], a, bv);
            mx[2] = fmaxf(mx[2], a); mx[3] = fmaxf(mx[3], bv);
        }
#pragma unroll
        for (int l = 0; l < 4; l++)
            red[kt * D + dt * 4 + l] = mx[l];
        WBAR();
        {
            float v = red[tid];
#pragma unroll
            for (int q = 1; q < 4; q++) v = fmaxf(v, red[q * D + tid]);
            float adj = Wsh[128 * D + tid] * s_cc[0]
                      + Wsh[129 * D + tid] * s_cc[1]
                      + Wsh[130 * D + tid] * s_cc[2];
            float o = v - adj + biasv;
            o = o > 0.f ? o : 0.f;
            out_fea[((size_t)b * D + tid) * S + s] = o;
        }
        WBAR();
    }
}

// =======================  fused persistent kernel  ======================
__global__ void __launch_bounds__(512, 1) fused_kernel(
    const float* __restrict__ coor, const float* __restrict__ fea,
    const float* __restrict__ W, const float* __restrict__ bb,
    const float* __restrict__ gamma, const float* __restrict__ beta,
    const float* __restrict__ mean, const float* __restrict__ var,
    float* __restrict__ out_coor, float* __restrict__ out_fea) {
    extern __shared__ float smem[];
    int cta = blockIdx.x, tid = threadIdx.x;
    if (cta < NFPS) {
        fps_block(coor, cta, tid, smem);
    } else {
        worker_block(coor, fea, W, bb, gamma, beta, mean, var,
                     out_coor, out_fea, smem, cta - NFPS, tid);
    }
}

// ---------------- launch ----------------
extern "C" void kernel_launch(void* const* d_in, const int* in_sizes, int n_in,
                              void* d_out, int out_size) {
    const float* coor  = (const float*)d_in[0];
    const float* fea   = (const float*)d_in[1];
    const float* W     = (const float*)d_in[2];
    const float* bb    = (const float*)d_in[3];
    const float* gamma = (const float*)d_in[4];
    const float* beta  = (const float*)d_in[5];
    const float* mean  = (const float*)d_in[6];
    const float* var   = (const float*)d_in[7];

    float* out      = (float*)d_out;
    float* out_coor = out;              // (B,3,S)
    float* out_fea  = out + B * 3 * S;  // (B,2C,S)

    init_kernel<<<1, 32>>>();

    const int smem_bytes = (CP * D + CP * K + 4 * D) * 4;  // 156160 B (fps needs 131072)
    cudaFuncSetAttribute(fused_kernel, cudaFuncAttributeMaxDynamicSharedMemorySize, smem_bytes);
    fused_kernel<<<NCTA, 512, smem_bytes>>>(coor, fea, W, bb, gamma, beta,
                                            mean, var, out_coor, out_fea);
}